// round 1
// baseline (speedup 1.0000x reference)
#include <cuda_runtime.h>
#include <stdint.h>

#define N_NODES 50000
#define N_EDGES 1000000
#define IN_F 128
#define OUT_F 64

// Scratch: support = features @ W  [N_NODES, OUT_F]
__device__ float g_support[N_NODES * OUT_F];

// ---------------------------------------------------------------------------
// Kernel 1: dense GEMM  support = features @ W
// Block: 256 threads, 8 rows per block. W (128x64 fp32 = 32KB) staged in smem.
// Each thread: one row (tid/32), two contiguous output cols (2*(tid%32)).
// ---------------------------------------------------------------------------
__global__ __launch_bounds__(256) void gemm_kernel(
    const float* __restrict__ feat,   // [N_NODES, IN_F]
    const float* __restrict__ W,      // [IN_F, OUT_F]
    float* __restrict__ support)      // [N_NODES, OUT_F]
{
    __shared__ float Ws[IN_F * OUT_F];     // 32 KB
    __shared__ float Fs[8][IN_F];          // 4 KB

    const int tid = threadIdx.x;

    // Cooperative load of W: 8192 floats = 2048 float4, 8 per thread
    {
        const float4* Wv = reinterpret_cast<const float4*>(W);
        float4* Wsv = reinterpret_cast<float4*>(Ws);
        #pragma unroll
        for (int i = 0; i < 8; i++)
            Wsv[tid + i * 256] = Wv[tid + i * 256];
    }

    // Load 8 feature rows: 1024 floats = 256 float4, 1 per thread
    const int row_base = blockIdx.x * 8;
    {
        const float4* Fv = reinterpret_cast<const float4*>(feat + (size_t)row_base * IN_F);
        // Fs is [8][128] contiguous = 256 float4
        reinterpret_cast<float4*>(&Fs[0][0])[tid] = Fv[tid];
    }
    __syncthreads();

    const int r = tid >> 5;          // 0..7
    const int c = (tid & 31) * 2;    // 0,2,..,62
    const int row = row_base + r;

    float acc0 = 0.f, acc1 = 0.f;
    #pragma unroll
    for (int k = 0; k < IN_F; k++) {
        const float f = Fs[r][k];
        acc0 += f * Ws[k * OUT_F + c];
        acc1 += f * Ws[k * OUT_F + c + 1];
    }

    float2 out2 = make_float2(acc0, acc1);
    reinterpret_cast<float2*>(support + (size_t)row * OUT_F)[c >> 1] = out2;
}

// ---------------------------------------------------------------------------
// Kernel 2: init output with bias broadcast
// ---------------------------------------------------------------------------
__global__ __launch_bounds__(256) void bias_init_kernel(
    float* __restrict__ out, const float* __restrict__ b)
{
    __shared__ float bs[OUT_F];
    if (threadIdx.x < OUT_F) bs[threadIdx.x] = b[threadIdx.x];
    __syncthreads();
    const int64_t total = (int64_t)N_NODES * OUT_F;
    int64_t i = (int64_t)blockIdx.x * blockDim.x + threadIdx.x;
    const int64_t stride = (int64_t)gridDim.x * blockDim.x;
    for (; i < total; i += stride)
        out[i] = bs[i & (OUT_F - 1)];
}

// ---------------------------------------------------------------------------
// Kernel 3: edge scatter.  One warp per edge; each lane owns a float2 column
// pair. atomicAdd without return -> REDG.
// ---------------------------------------------------------------------------
__global__ __launch_bounds__(256) void scatter_kernel(
    const int* __restrict__ edge_src,
    const int* __restrict__ edge_dst,
    const float* __restrict__ edge_w,
    const float* __restrict__ support,
    float* __restrict__ out)
{
    const int warp_id = (blockIdx.x * blockDim.x + threadIdx.x) >> 5;
    if (warp_id >= N_EDGES) return;
    const int lane = threadIdx.x & 31;

    const int src = edge_src[warp_id];
    const int dst = edge_dst[warp_id];
    const float w = edge_w[warp_id];

    const float2 s = reinterpret_cast<const float2*>(
        support + (size_t)src * OUT_F)[lane];

    float* o = out + (size_t)dst * OUT_F + lane * 2;
    atomicAdd(o,     s.x * w);
    atomicAdd(o + 1, s.y * w);
}

// ---------------------------------------------------------------------------
extern "C" void kernel_launch(void* const* d_in, const int* in_sizes, int n_in,
                              void* d_out, int out_size)
{
    const float* features = (const float*)d_in[0];
    const int*   edge_src = (const int*)d_in[1];
    const int*   edge_dst = (const int*)d_in[2];
    const float* edge_w   = (const float*)d_in[3];
    const float* W        = (const float*)d_in[4];
    const float* b        = (const float*)d_in[5];
    float* out = (float*)d_out;

    float* support;
    cudaGetSymbolAddress((void**)&support, g_support);

    // 1) support = features @ W
    gemm_kernel<<<N_NODES / 8, 256>>>(features, W, support);

    // 2) out = b (broadcast)
    bias_init_kernel<<<2048, 256>>>(out, b);

    // 3) scatter-add over edges (8 warps/block, 1 warp/edge)
    const int blocks = (N_EDGES * 32 + 255) / 256;
    scatter_kernel<<<blocks, 256>>>(edge_src, edge_dst, edge_w, support, out);
}

// round 2
// speedup vs baseline: 2.1501x; 2.1501x over previous
#include <cuda_runtime.h>
#include <stdint.h>

#define N_NODES 50000
#define N_EDGES 1000000
#define IN_F 128
#define OUT_F 64
#define TILE_ROWS 128

// Scratch: support = features @ W  [N_NODES, OUT_F]
__device__ float g_support[N_NODES * OUT_F];

// ---------------------------------------------------------------------------
// Kernel 1: register-tiled GEMM  support = features @ W, fused out = b init.
// Block: 256 threads, tile 128 rows x 64 cols. Per thread: 8 rows x 4 cols.
// W fully staged in smem (32KB); features staged in 16-wide k-chunks (8KB).
// ---------------------------------------------------------------------------
__global__ __launch_bounds__(256) void gemm_bias_kernel(
    const float* __restrict__ feat,   // [N_NODES, IN_F]
    const float* __restrict__ W,      // [IN_F, OUT_F]
    const float* __restrict__ b,      // [OUT_F]
    float* __restrict__ support,      // [N_NODES, OUT_F]
    float* __restrict__ out)          // [N_NODES, OUT_F]
{
    __shared__ float Ws[IN_F][OUT_F];     // 32 KB
    __shared__ float Fs[TILE_ROWS][16];   // 8 KB (one k-chunk)

    const int tid = threadIdx.x;

    // Cooperative load of full W: 8192 floats = 2048 float4, 8 per thread
    {
        const float4* Wv = reinterpret_cast<const float4*>(W);
        float4* Wsv = reinterpret_cast<float4*>(&Ws[0][0]);
        #pragma unroll
        for (int i = 0; i < 8; i++)
            Wsv[tid + i * 256] = Wv[tid + i * 256];
    }

    const int row_base = blockIdx.x * TILE_ROWS;
    const int cg = tid & 15;     // col group: cols [4*cg, 4*cg+4)
    const int rg = tid >> 4;     // row group: rows [8*rg, 8*rg+8)

    float acc[8][4] = {};

    #pragma unroll 1
    for (int kc = 0; kc < IN_F / 16; kc++) {
        __syncthreads();   // prev chunk consumed (and Ws ready on kc==0)
        // Load Fs chunk: 128 rows x 16 k = 512 float4, 2 per thread
        #pragma unroll
        for (int i = 0; i < 2; i++) {
            int idx = tid + i * 256;        // 0..511
            int row = idx >> 2;
            int q = idx & 3;
            int grow = row_base + row;
            float4 v = make_float4(0.f, 0.f, 0.f, 0.f);
            if (grow < N_NODES)
                v = *reinterpret_cast<const float4*>(
                        feat + (size_t)grow * IN_F + kc * 16 + q * 4);
            *reinterpret_cast<float4*>(&Fs[row][q * 4]) = v;
        }
        __syncthreads();

        #pragma unroll
        for (int kk = 0; kk < 16; kk++) {
            const int k = kc * 16 + kk;
            const float4 w4 = *reinterpret_cast<const float4*>(&Ws[k][cg * 4]);
            #pragma unroll
            for (int r = 0; r < 8; r++) {
                const float f = Fs[rg * 8 + r][kk];
                acc[r][0] += f * w4.x;
                acc[r][1] += f * w4.y;
                acc[r][2] += f * w4.z;
                acc[r][3] += f * w4.w;
            }
        }
    }

    // Epilogue: store support tile; also initialize out tile with bias.
    const float4 b4 = *reinterpret_cast<const float4*>(b + cg * 4);
    #pragma unroll
    for (int r = 0; r < 8; r++) {
        const int grow = row_base + rg * 8 + r;
        if (grow < N_NODES) {
            *reinterpret_cast<float4*>(support + (size_t)grow * OUT_F + cg * 4) =
                make_float4(acc[r][0], acc[r][1], acc[r][2], acc[r][3]);
            *reinterpret_cast<float4*>(out + (size_t)grow * OUT_F + cg * 4) = b4;
        }
    }
}

// ---------------------------------------------------------------------------
// Kernel 2: edge scatter with vector reductions.
// Block = 256 threads = 8 warps, handles 64 edges. Edge metadata staged in
// smem. Each warp: 2 edges per iteration (16 lanes x float4 = 64 cols),
// 4 iterations. red.global.add.v4.f32 -> one REDG.128 per lane.
// ---------------------------------------------------------------------------
__global__ __launch_bounds__(256) void scatter_kernel(
    const int* __restrict__ edge_src,
    const int* __restrict__ edge_dst,
    const float* __restrict__ edge_w,
    const float* __restrict__ support,
    float* __restrict__ out)
{
    __shared__ int   s_src[64];
    __shared__ int   s_dst[64];
    __shared__ float s_w[64];

    const int tid = threadIdx.x;
    const int ebase = blockIdx.x * 64;
    if (tid < 64) {
        s_src[tid] = edge_src[ebase + tid];
        s_dst[tid] = edge_dst[ebase + tid];
        s_w[tid]   = edge_w[ebase + tid];
    }
    __syncthreads();

    const int wi   = tid >> 5;
    const int lane = tid & 31;
    const int half = lane >> 4;   // which edge of the pair
    const int li   = lane & 15;   // float4 index within the 64-col row

    #pragma unroll
    for (int it = 0; it < 4; it++) {
        const int le = wi * 8 + it * 2 + half;   // 0..63
        const int   src = s_src[le];
        const int   dst = s_dst[le];
        const float w   = s_w[le];

        const float4 s = *reinterpret_cast<const float4*>(
            support + (size_t)src * OUT_F + li * 4);

        float* o = out + (size_t)dst * OUT_F + li * 4;
        asm volatile("red.global.add.v4.f32 [%0], {%1, %2, %3, %4};"
                     :: "l"(o), "f"(s.x * w), "f"(s.y * w),
                        "f"(s.z * w), "f"(s.w * w)
                     : "memory");
    }
}

// ---------------------------------------------------------------------------
extern "C" void kernel_launch(void* const* d_in, const int* in_sizes, int n_in,
                              void* d_out, int out_size)
{
    const float* features = (const float*)d_in[0];
    const int*   edge_src = (const int*)d_in[1];
    const int*   edge_dst = (const int*)d_in[2];
    const float* edge_w   = (const float*)d_in[3];
    const float* W        = (const float*)d_in[4];
    const float* b        = (const float*)d_in[5];
    float* out = (float*)d_out;

    float* support;
    cudaGetSymbolAddress((void**)&support, g_support);

    // 1) support = features @ W, out = b
    const int gemm_blocks = (N_NODES + TILE_ROWS - 1) / TILE_ROWS;  // 391
    gemm_bias_kernel<<<gemm_blocks, 256>>>(features, W, b, support, out);

    // 2) scatter-add over edges: 64 edges/block
    scatter_kernel<<<N_EDGES / 64, 256>>>(edge_src, edge_dst, edge_w,
                                          support, out);
}